// round 2
// baseline (speedup 1.0000x reference)
#include <cuda_runtime.h>
#include <math.h>

// ---------------- fixed problem shape ----------------
#define D_MODEL 1024
#define D_FF    4096
#define T_SEQ   4096
#define B_BATCH 4
#define N_TOK   (B_BATCH * T_SEQ)   // 16384 rows
#define H_HEADS 16
#define DK      64

// ---------------- device scratch (no cudaMalloc allowed) ----------------
__device__ float g_x1[(size_t)N_TOK * D_MODEL];
__device__ float g_q [(size_t)N_TOK * D_MODEL];
__device__ float g_k [(size_t)N_TOK * D_MODEL];
__device__ float g_v [(size_t)N_TOK * D_MODEL];
__device__ float g_os[(size_t)N_TOK * D_MODEL];
__device__ float g_o2[(size_t)N_TOK * D_MODEL];
__device__ float g_q2[(size_t)N_TOK * D_MODEL];
__device__ float g_h [(size_t)N_TOK * D_FF];
__device__ float g_y [(size_t)N_TOK * D_MODEL];

// ---------------- LayerNorm (optionally fused residual add) ----------------
// one block (256 threads) per row of 1024 floats
__global__ void __launch_bounds__(256) ln_kernel(
    const float* __restrict__ in, const float* __restrict__ res,
    const float* __restrict__ gam, const float* __restrict__ bet,
    float* __restrict__ out)
{
    const int row = blockIdx.x;
    const int tid = threadIdx.x;
    const size_t base = (size_t)row * D_MODEL;

    float4 v = *(const float4*)(in + base + tid * 4);
    if (res) {
        float4 r = *(const float4*)(res + base + tid * 4);
        v.x += r.x; v.y += r.y; v.z += r.z; v.w += r.w;
    }
    float s  = v.x + v.y + v.z + v.w;
    float ss = v.x * v.x + v.y * v.y + v.z * v.z + v.w * v.w;

    #pragma unroll
    for (int o = 16; o > 0; o >>= 1) {
        s  += __shfl_down_sync(0xffffffffu, s,  o);
        ss += __shfl_down_sync(0xffffffffu, ss, o);
    }
    __shared__ float sh_s[8], sh_ss[8];
    const int w = tid >> 5, l = tid & 31;
    if (l == 0) { sh_s[w] = s; sh_ss[w] = ss; }
    __syncthreads();
    if (tid == 0) {
        float ts = 0.f, tss = 0.f;
        #pragma unroll
        for (int i = 0; i < 8; i++) { ts += sh_s[i]; tss += sh_ss[i]; }
        sh_s[0] = ts; sh_ss[0] = tss;
    }
    __syncthreads();
    const float mu  = sh_s[0] * (1.0f / D_MODEL);
    const float var = sh_ss[0] * (1.0f / D_MODEL) - mu * mu;
    const float inv = rsqrtf(var + 1e-6f);

    float4 g4 = *(const float4*)(gam + tid * 4);
    float4 b4 = *(const float4*)(bet + tid * 4);
    float4 o4;
    o4.x = (v.x - mu) * inv * g4.x + b4.x;
    o4.y = (v.y - mu) * inv * g4.y + b4.y;
    o4.z = (v.z - mu) * inv * g4.z + b4.z;
    o4.w = (v.w - mu) * inv * g4.w + b4.w;
    *(float4*)(out + base + tid * 4) = o4;
}

// ---------------- per-token head-mixing attention ----------------
// attn[h,g] = softmax_g( q[h].k[g] / sqrt(64) ); o[h,d] = sum_g attn[h,g] v[g,d]
// output written in the "faithful head-major reshape" scrambled layout:
//   o_scr[b*T*D + h*T*DK + t*DK + d]
__global__ void __launch_bounds__(256) attn_kernel(
    const float* __restrict__ q, const float* __restrict__ k,
    const float* __restrict__ v, float* __restrict__ o_scr)
{
    const int row = blockIdx.x;       // b*T + t
    const int tid = threadIdx.x;      // 256
    __shared__ float sq[D_MODEL], sk[D_MODEL], sv[D_MODEL];
    __shared__ float sS[H_HEADS][H_HEADS + 1];

    const size_t base = (size_t)row * D_MODEL;
    ((float4*)sq)[tid] = *(const float4*)(q + base + tid * 4);
    ((float4*)sk)[tid] = *(const float4*)(k + base + tid * 4);
    ((float4*)sv)[tid] = *(const float4*)(v + base + tid * 4);
    __syncthreads();

    // scores: one (h,g) pair per thread
    {
        const int h = tid >> 4, g = tid & 15;
        float s = 0.f;
        #pragma unroll
        for (int d = 0; d < DK; d++) s += sq[h * DK + d] * sk[g * DK + d];
        sS[h][g] = s * 0.125f;   // 1/sqrt(64)
    }
    __syncthreads();

    // softmax over g, one head per thread (16 active)
    if (tid < H_HEADS) {
        float mx = -1e30f;
        #pragma unroll
        for (int g = 0; g < H_HEADS; g++) mx = fmaxf(mx, sS[tid][g]);
        float sum = 0.f;
        #pragma unroll
        for (int g = 0; g < H_HEADS; g++) {
            float e = expf(sS[tid][g] - mx);
            sS[tid][g] = e; sum += e;
        }
        const float invs = 1.0f / sum;
        #pragma unroll
        for (int g = 0; g < H_HEADS; g++) sS[tid][g] *= invs;
    }
    __syncthreads();

    // o[h,d] = sum_g P[h,g] * v[g,d]; write scrambled
    const int b = row / T_SEQ;
    const int t = row % T_SEQ;
    float* ob = o_scr + (size_t)b * T_SEQ * D_MODEL + (size_t)t * DK;
    #pragma unroll
    for (int i = 0; i < 4; i++) {
        const int idx = i * 256 + tid;
        const int h = idx >> 6, d = idx & 63;
        float acc = 0.f;
        #pragma unroll
        for (int g = 0; g < H_HEADS; g++) acc += sS[h][g] * sv[g * DK + d];
        ob[(size_t)h * T_SEQ * DK + d] = acc;
    }
}

// ---------------- fp32 SGEMM: C[M,Nn] = A[M,K] @ B[K,Nn] (+epilogue) --------
// BM=BN=128, BK=16, 256 threads, 8x8 per thread, float4 vectorized.
// EPI: 0 = none, 1 = bias + exact GELU, 2 = bias + residual add
template<int EPI>
__global__ void __launch_bounds__(256) sgemm_kernel(
    const float* __restrict__ A, const float* __restrict__ B,
    float* __restrict__ C, int K, int Nn,
    const float* __restrict__ bias, const float* __restrict__ res)
{
    __shared__ float As[16][128];
    __shared__ float Bs[16][128];

    const int tid = threadIdx.x;
    const int bm = blockIdx.y, bn = blockIdx.x;
    const float* Ab = A + (size_t)bm * 128 * K;
    const float* Bb = B + (size_t)bn * 128;

    const int tr = (tid >> 4) << 3;   // 0..120 row in tile
    const int tc = (tid & 15) << 3;   // 0..120 col in tile

    const int ar = tid >> 2;          // 0..63
    const int ac = (tid & 3) << 2;    // 0,4,8,12
    const int br = tid >> 5;          // 0..7
    const int bc = (tid & 31) << 2;   // 0..124

    float acc[8][8];
    #pragma unroll
    for (int i = 0; i < 8; i++)
        #pragma unroll
        for (int j = 0; j < 8; j++) acc[i][j] = 0.f;

    for (int k0 = 0; k0 < K; k0 += 16) {
        float4 a0 = *(const float4*)(Ab + (size_t)ar * K + k0 + ac);
        float4 a1 = *(const float4*)(Ab + (size_t)(ar + 64) * K + k0 + ac);
        float4 b0 = *(const float4*)(Bb + (size_t)(k0 + br) * Nn + bc);
        float4 b1 = *(const float4*)(Bb + (size_t)(k0 + br + 8) * Nn + bc);

        As[ac + 0][ar] = a0.x; As[ac + 1][ar] = a0.y;
        As[ac + 2][ar] = a0.z; As[ac + 3][ar] = a0.w;
        As[ac + 0][ar + 64] = a1.x; As[ac + 1][ar + 64] = a1.y;
        As[ac + 2][ar + 64] = a1.z; As[ac + 3][ar + 64] = a1.w;
        *(float4*)&Bs[br][bc]     = b0;
        *(float4*)&Bs[br + 8][bc] = b1;
        __syncthreads();

        #pragma unroll
        for (int kk = 0; kk < 16; kk++) {
            float4 ra0 = *(const float4*)&As[kk][tr];
            float4 ra1 = *(const float4*)&As[kk][tr + 4];
            float4 rb0 = *(const float4*)&Bs[kk][tc];
            float4 rb1 = *(const float4*)&Bs[kk][tc + 4];
            const float ra[8] = {ra0.x, ra0.y, ra0.z, ra0.w, ra1.x, ra1.y, ra1.z, ra1.w};
            const float rb[8] = {rb0.x, rb0.y, rb0.z, rb0.w, rb1.x, rb1.y, rb1.z, rb1.w};
            #pragma unroll
            for (int i = 0; i < 8; i++)
                #pragma unroll
                for (int j = 0; j < 8; j++)
                    acc[i][j] += ra[i] * rb[j];
        }
        __syncthreads();
    }

    const size_t rowBase = (size_t)bm * 128 + tr;
    const int    colBase = bn * 128 + tc;
    #pragma unroll
    for (int i = 0; i < 8; i++) {
        float o[8];
        #pragma unroll
        for (int j = 0; j < 8; j++) {
            float val = acc[i][j];
            if (EPI == 1) {
                val += bias[colBase + j];
                val = 0.5f * val * (1.0f + erff(val * 0.70710678118654752f));
            } else if (EPI == 2) {
                val += bias[colBase + j]
                     + res[(rowBase + i) * (size_t)Nn + colBase + j];
            }
            o[j] = val;
        }
        float* crow = C + (rowBase + i) * (size_t)Nn + colBase;
        *(float4*)(crow)     = make_float4(o[0], o[1], o[2], o[3]);
        *(float4*)(crow + 4) = make_float4(o[4], o[5], o[6], o[7]);
    }
}

// ---------------- launch ----------------
extern "C" void kernel_launch(void* const* d_in, const int* in_sizes, int n_in,
                              void* d_out, int out_size)
{
    const float* x     = (const float*)d_in[0];
    const float* wq    = (const float*)d_in[1];
    const float* wk    = (const float*)d_in[2];
    const float* wv    = (const float*)d_in[3];
    const float* wo    = (const float*)d_in[4];
    const float* ln1g  = (const float*)d_in[5];
    const float* ln1b  = (const float*)d_in[6];
    const float* w1    = (const float*)d_in[7];
    const float* b1    = (const float*)d_in[8];
    const float* w2    = (const float*)d_in[9];
    const float* b2    = (const float*)d_in[10];
    const float* ln2g  = (const float*)d_in[11];
    const float* ln2b  = (const float*)d_in[12];
    float* out = (float*)d_out;

    float *x1, *q, *k, *v, *os, *o2, *q2, *h, *y;
    cudaGetSymbolAddress((void**)&x1, g_x1);
    cudaGetSymbolAddress((void**)&q,  g_q);
    cudaGetSymbolAddress((void**)&k,  g_k);
    cudaGetSymbolAddress((void**)&v,  g_v);
    cudaGetSymbolAddress((void**)&os, g_os);
    cudaGetSymbolAddress((void**)&o2, g_o2);
    cudaGetSymbolAddress((void**)&q2, g_q2);
    cudaGetSymbolAddress((void**)&h,  g_h);
    cudaGetSymbolAddress((void**)&y,  g_y);

    const dim3 gD(D_MODEL / 128, N_TOK / 128);   // (8, 128)
    const dim3 gF(D_FF    / 128, N_TOK / 128);   // (32, 128)

    // 1) x1 = LN(x)
    ln_kernel<<<N_TOK, 256>>>(x, nullptr, ln1g, ln1b, x1);
    // 2) q,k,v = x1 @ {wq,wk,wv}
    sgemm_kernel<0><<<gD, 256>>>(x1, wq, q, D_MODEL, D_MODEL, nullptr, nullptr);
    sgemm_kernel<0><<<gD, 256>>>(x1, wk, k, D_MODEL, D_MODEL, nullptr, nullptr);
    sgemm_kernel<0><<<gD, 256>>>(x1, wv, v, D_MODEL, D_MODEL, nullptr, nullptr);
    // 3) per-token head-mix attention, scrambled output layout
    attn_kernel<<<N_TOK, 256>>>(q, k, v, os);
    // 4) o2 = o_scr @ wo
    sgemm_kernel<0><<<gD, 256>>>(os, wo, o2, D_MODEL, D_MODEL, nullptr, nullptr);
    // 5) q2 = LN(o2 + x) with ln1 params (faithful reuse)
    ln_kernel<<<N_TOK, 256>>>(o2, x, ln1g, ln1b, q2);
    // 6) h = gelu(q2 @ w1 + b1)
    sgemm_kernel<1><<<gF, 256>>>(q2, w1, h, D_MODEL, D_FF, b1, nullptr);
    // 7) y = h @ w2 + b2 + q2
    sgemm_kernel<2><<<gD, 256>>>(h, w2, y, D_FF, D_MODEL, b2, q2);
    // 8) out = LN(y) with ln2 params
    ln_kernel<<<N_TOK, 256>>>(y, nullptr, ln2g, ln2b, out);
}